// round 17
// baseline (speedup 1.0000x reference)
#include <cuda_runtime.h>
#include <cuda_fp16.h>
#include <cstdint>
#include <cstddef>

#define BATCH 16
#define CIN   512
#define COUT  512
#define NPIX  4096
#define MOD_SCALE  0.044194173824159216f
#define CONV_SCALE 0.014731391274719739f

// Winograd F(2x2,3x3): 1024 tiles/image, 16 transform points (u)
// GEMM per (u,b): M_u[512co,1024t] = W_u[512co,512ci] * D_u[512ci,1024t]
// Persistent CTAs: 456 resident (3/SM), 128 threads, 4 warps of 64co x 64t,
// rolling 2-stage cp.async across tiles.

#define DSTR   136                          // 128 tiles + 8 pad words (8 mod 32 -> conflict-free)
#define DCH_B  (32*DSTR*4)                  // 17408 B per D stage (32 cipairs)
#define WCH_B  16384                        // 64ci x 128co fp16
#define STAGE_B (DCH_B + WCH_B)             // 33792 B
#define GEMM_SMEM (2*STAGE_B)               // 67584 B (2-stage; 3 CTAs/SM)
#define GEMM_GRID 456

#define PSTR 72                             // dtrans smem plane stride (floats)

// ---------------- device scratch ----------------
__device__ float g_s[BATCH*CIN];
__device__ float g_wsq[COUT*CIN];
__device__ __align__(128) __half   g_wg[16*4*16*4096];                 // 8 MB transformed W, frag-packed
__device__ __align__(128) uint32_t g_d[(size_t)16*16*256*1024];        // 268 MB transformed input (f16x2 ci-pairs)
__device__ __align__(128) __half   g_m[(size_t)16*16*512*1024];        // 268 MB GEMM output M

// ---------------- mod: s[b][ci] = style @ (mod_weight*MOD_SCALE)^T + bias ----------------
__global__ __launch_bounds__(512) void mod_kernel(const float* __restrict__ style,
                                                  const float* __restrict__ mod_weight,
                                                  const float* __restrict__ mod_bias){
    __shared__ float st[512];
    int b = blockIdx.x, t = threadIdx.x;
    st[t] = style[b*512 + t];
    __syncthreads();
    const float* wr = mod_weight + t*512;
    float acc = 0.f;
    #pragma unroll 8
    for (int j = 0; j < 512; j++) acc = fmaf(st[j], wr[j], acc);
    g_s[b*512 + t] = acc * MOD_SCALE + mod_bias[t];
}

// ---------------- dtrans (grid y<16) + fused wtrans (grid y>=16) ----------------
__global__ __launch_bounds__(256) void dtrans_kernel(const float* __restrict__ x,
                                                     const float* __restrict__ w){
    __shared__ float sp[2*66*PSTR];        // two padded planes, 38016 B
    int tid = threadIdx.x;

    if (blockIdx.y >= 16){
        // ---- wtrans: U = G g G^T (frag-packed fp16) + fused wsq ----
        int blk = (blockIdx.y - 16)*256 + blockIdx.x;   // 0..1023
        int i = blk*256 + tid;                          // 262144 = co*512+ci
        int co = i >> 9, ci = i & 511;
        const float* p = w + (size_t)i*9;
        float g[3][3];
        float sq = 0.f;
        #pragma unroll
        for (int r = 0; r < 3; r++)
            #pragma unroll
            for (int c = 0; c < 3; c++){ g[r][c] = p[r*3+c]; sq = fmaf(g[r][c], g[r][c], sq); }
        g_wsq[i] = sq;
        float t[4][3];
        #pragma unroll
        for (int c = 0; c < 3; c++){
            t[0][c] = g[0][c];
            t[1][c] = 0.5f*(g[0][c]+g[1][c]+g[2][c]);
            t[2][c] = 0.5f*(g[0][c]-g[1][c]+g[2][c]);
            t[3][c] = g[2][c];
        }
        float U[16];
        #pragma unroll
        for (int r = 0; r < 4; r++){
            U[r*4+0] = t[r][0];
            U[r*4+1] = 0.5f*(t[r][0]+t[r][1]+t[r][2]);
            U[r*4+2] = 0.5f*(t[r][0]-t[r][1]+t[r][2]);
            U[r*4+3] = t[r][2];
        }
        int kc = ci>>5, c5 = ci&31, ks = c5>>4, cc = c5&15;
        int lane = (co&7)*4 + ((cc>>1)&3);
        int r    = ((co>>3)&1) + ((cc>>3)&1)*2;
        int mt   = (co>>4)&7, cb = co>>7;
        size_t boff = ((size_t)(cb*16 + kc))*4096 + (size_t)(((ks*8+mt)*32+lane)<<3) + r*2 + (cc&1);
        #pragma unroll
        for (int u = 0; u < 16; u++)
            g_wg[boff + (size_t)u*262144] = __float2half_rn(U[u]);
        return;
    }

    // ---- dtrans: D = B^T x B * s ----
    int cp = blockIdx.x, b = blockIdx.y;
    const float* x0 = x + ((size_t)(b*512 + cp*2))*NPIX;
    const float* x1 = x0 + NPIX;
    float s0 = g_s[b*512 + cp*2];
    float s1 = g_s[b*512 + cp*2 + 1];

    float4 z = make_float4(0.f,0.f,0.f,0.f);
    for (int i = tid; i < 2*66*PSTR/4; i += 256) ((float4*)sp)[i] = z;
    __syncthreads();

    unsigned spu = (unsigned)__cvta_generic_to_shared(sp);
    #pragma unroll
    for (int k = 0; k < 8; k++){
        int t = tid + k*256;               // 0..2047
        int p  = t >> 10;
        int rm = t & 1023;
        int ir = rm >> 4, ch = rm & 15;
        unsigned dst = spu + (unsigned)((p*66*PSTR + (ir+1)*PSTR + 4 + ch*4)*4);
        const float* src = (p ? x1 : x0) + ir*64 + ch*4;
        asm volatile("cp.async.cg.shared.global [%0], [%1], 16;" :: "r"(dst), "l"(src));
    }
    asm volatile("cp.async.commit_group;");
    asm volatile("cp.async.wait_group 0;");
    __syncthreads();

    const float* sp0 = sp;
    const float* sp1 = sp + 66*PSTR;

    auto tilepack = [&](int i, int j, uint32_t* outp){
        float dx[4][4], dy[4][4];
        int base = (2*i)*PSTR + 2*j + 3;
        #pragma unroll
        for (int rr = 0; rr < 4; rr++)
            #pragma unroll
            for (int cc = 0; cc < 4; cc++){
                dx[rr][cc] = sp0[base + rr*PSTR + cc] * s0;
                dy[rr][cc] = sp1[base + rr*PSTR + cc] * s1;
            }
        float tx[4][4], ty[4][4];
        #pragma unroll
        for (int c = 0; c < 4; c++){
            tx[0][c] = dx[0][c] - dx[2][c];  ty[0][c] = dy[0][c] - dy[2][c];
            tx[1][c] = dx[1][c] + dx[2][c];  ty[1][c] = dy[1][c] + dy[2][c];
            tx[2][c] = dx[2][c] - dx[1][c];  ty[2][c] = dy[2][c] - dy[1][c];
            tx[3][c] = dx[1][c] - dx[3][c];  ty[3][c] = dy[1][c] - dy[3][c];
        }
        #pragma unroll
        for (int r = 0; r < 4; r++){
            __half2 h0 = __floats2half2_rn(tx[r][0] - tx[r][2], ty[r][0] - ty[r][2]);
            __half2 h1 = __floats2half2_rn(tx[r][1] + tx[r][2], ty[r][1] + ty[r][2]);
            __half2 h2 = __floats2half2_rn(tx[r][2] - tx[r][1], ty[r][2] - ty[r][1]);
            __half2 h3 = __floats2half2_rn(tx[r][1] - tx[r][3], ty[r][1] - ty[r][3]);
            outp[r*4+0] = *(uint32_t*)&h0;
            outp[r*4+1] = *(uint32_t*)&h1;
            outp[r*4+2] = *(uint32_t*)&h2;
            outp[r*4+3] = *(uint32_t*)&h3;
        }
    };

    #pragma unroll
    for (int pp = 0; pp < 2; pp++){
        int q = pp*256 + tid;              // tile-pair index: tiles 2q, 2q+1
        int i = q >> 4, j0 = (q & 15)*2;
        uint32_t ua[16], ub[16];
        tilepack(i, j0,   ua);
        tilepack(i, j0+1, ub);
        size_t gbase = ((size_t)(b*16)*256 + cp)*1024 + 2*q;
        #pragma unroll
        for (int u = 0; u < 16; u++)
            *(uint2*)&g_d[gbase + (size_t)u*262144] = make_uint2(ua[u], ub[u]);
    }
}

// ---------------- GEMM: fp16 m16n8k16, fp32 accum, persistent CTAs, rolling 2-stage, occ 3 ----------------
__device__ __forceinline__ void mma_f16(float* c, uint32_t a0,uint32_t a1,uint32_t a2,uint32_t a3,
                                        uint32_t b0,uint32_t b1){
    asm volatile("mma.sync.aligned.m16n8k16.row.col.f32.f16.f16.f32 "
        "{%0,%1,%2,%3}, {%4,%5,%6,%7}, {%8,%9}, {%0,%1,%2,%3};"
        : "+f"(c[0]), "+f"(c[1]), "+f"(c[2]), "+f"(c[3])
        : "r"(a0), "r"(a1), "r"(a2), "r"(a3), "r"(b0), "r"(b1));
}

__global__ __launch_bounds__(128,3) void gemm_kernel(){
    extern __shared__ char smem[];
    const int tid  = threadIdx.x;
    const int lane = tid & 31;
    const int warp = tid >> 5;        // 0..3
    const int wm   = warp >> 1;       // co half (64)
    const int wn   = warp & 1;        // tile half (64)
    const int bx   = blockIdx.x;

    unsigned sm_u = (unsigned)__cvta_generic_to_shared(smem);

    const int njobs = (8192 - bx + GEMM_GRID - 1) / GEMM_GRID;
    const int totg  = njobs * 8;

    auto issue = [&](int g, int s){
        int jw = g >> 3, kc = g & 7;
        int wk = bx + jw * GEMM_GRID;
        int x = wk & 31, ub = wk >> 5;
        int cb = x >> 3, nb = x & 7;
        const uint4* dsrc = (const uint4*)g_d + (size_t)ub*65536 + (size_t)(nb*32);
        const uint4* wsrc = (const uint4*)g_wg + (size_t)(ub & 15)*32768 + (size_t)cb*8192;
        unsigned base = sm_u + (unsigned)(s * STAGE_B);
        #pragma unroll
        for (int k = 0; k < 8; k++){
            int idx = tid + k*128;        // 0..1023
            int cp = idx >> 5, q = idx & 31;
            asm volatile("cp.async.cg.shared.global [%0], [%1], 16;"
                         :: "r"(base + (unsigned)((cp*DSTR + q*4)*4)),
                            "l"(dsrc + (size_t)(kc*32 + cp)*256 + q));
        }
        #pragma unroll
        for (int k = 0; k < 8; k++){
            int idx = tid + k*128;        // 0..1023
            asm volatile("cp.async.cg.shared.global [%0], [%1], 16;"
                         :: "r"(base + (unsigned)(DCH_B + idx*16)), "l"(wsrc + kc*1024 + idx));
        }
    };

    // prologue: one group in flight
    issue(0, 0);
    asm volatile("cp.async.commit_group;");
    int gl = 1;                            // next group to issue

    for (int jw = 0; jw < njobs; jw++){
        int wk = bx + jw * GEMM_GRID;
        int x = wk & 31, ub = wk >> 5;
        int cb = x >> 3, nb = x & 7;
        int tile0 = nb * 128;

        float acc[4][8][4];
        #pragma unroll
        for (int i=0;i<4;i++)
          #pragma unroll
          for (int j=0;j<8;j++)
            #pragma unroll
            for (int k=0;k<4;k++) acc[i][j][k]=0.f;

        for (int kc = 0; kc < 8; kc++){
            int g = jw*8 + kc;             // group being consumed this iteration
            // prefetch g+1 into stage (g+1)&1: last read at iteration g-1,
            // whose readers are fenced by that iteration's trailing barrier.
            if (gl < totg) issue(gl, gl & 1);
            asm volatile("cp.async.commit_group;");   // (empty group in tail keeps accounting)
            gl++;
            asm volatile("cp.async.wait_group 1;");   // group g complete; g+1 in flight
            __syncthreads();

            const uint32_t* xb = (const uint32_t*)(smem + (g & 1)*STAGE_B) + wn*64 + (lane >> 2);
            const float4*  w4 = (const float4*)(smem + (g & 1)*STAGE_B + DCH_B);

            #pragma unroll
            for (int ks = 0; ks < 4; ks++){
                const uint32_t* xp = xb + (ks*8 + (lane & 3)) * DSTR;
                uint32_t bf[8][2];
                #pragma unroll
                for (int nt = 0; nt < 8; nt++){
                    bf[nt][0] = xp[nt*8];
                    bf[nt][1] = xp[nt*8 + 4*DSTR];
                }
                #pragma unroll
                for (int mt = 0; mt < 4; mt++){
                    float4 a = w4[(ks>>1)*512 + (((ks&1)*8 + wm*4 + mt)*32 + lane)];
                    uint32_t a0=__float_as_uint(a.x), a1=__float_as_uint(a.y),
                             a2=__float_as_uint(a.z), a3=__float_as_uint(a.w);
                    #pragma unroll
                    for (int nt = 0; nt < 8; nt++)
                        mma_f16(acc[mt][nt], a0,a1,a2,a3, bf[nt][0], bf[nt][1]);
                }
            }
            // trailing barrier: stage g&1 must be fully read before iteration g+1
            // issues group g+2 into the same stage.
            __syncthreads();
        }

        #pragma unroll
        for (int mt = 0; mt < 4; mt++){
            int co = cb*128 + wm*64 + mt*16 + (lane >> 2);
            size_t rb = ((size_t)ub*512 + co)*1024;
            #pragma unroll
            for (int nt = 0; nt < 8; nt++){
                int tile = tile0 + wn*64 + nt*8 + (lane & 3)*2;
                __half2 v0 = __floats2half2_rn(acc[mt][nt][0], acc[mt][nt][1]);
                __half2 v1 = __floats2half2_rn(acc[mt][nt][2], acc[mt][nt][3]);
                *(__half2*)(g_m + rb + tile)          = v0;
                *(__half2*)(g_m + rb + 8*1024 + tile) = v1;
            }
        }
    }
}

// ---------------- inverse transform + fused demod: out = (A^T M A) * dscale ----------------
__global__ __launch_bounds__(256) void inv_kernel(float* __restrict__ out){
    __shared__ float red[256];
    int blk = blockIdx.x, b = blockIdx.y, tid = threadIdx.x;
    int half = tid >> 7;
    int lt   = tid & 127;
    int co = blk*2 + half;

    float partial = 0.f;
    #pragma unroll
    for (int k = 0; k < 4; k++){
        int ci = lt + k*128;
        float sv = g_s[b*512 + ci];
        partial = fmaf(sv*sv, g_wsq[co*512 + ci], partial);
    }
    red[tid] = partial;
    __syncthreads();
    #pragma unroll
    for (int off = 64; off > 0; off >>= 1){
        if (lt < off) red[tid] += red[tid + off];
        __syncthreads();
    }
    float ds = CONV_SCALE / sqrtf(CONV_SCALE*CONV_SCALE*red[half*128] + 1e-8f);

    int p = lt;
    const uint4* mp = (const uint4*)(g_m + ((size_t)(b*16)*512 + co)*1024);
    uint4 raw[16];
    #pragma unroll
    for (int u = 0; u < 16; u++) raw[u] = mp[(size_t)u*65536 + p];

    float* op = out + ((size_t)(b*512 + co))*NPIX;
    int i = p >> 2, jb = (p & 3)*16;

    #pragma unroll
    for (int sl = 0; sl < 4; sl++){
        float2 m[16];
        #pragma unroll
        for (int u = 0; u < 16; u++){
            uint32_t w = (sl==0) ? raw[u].x : (sl==1) ? raw[u].y : (sl==2) ? raw[u].z : raw[u].w;
            m[u] = __half22float2(*(__half2*)&w);
        }
        float2 p0[4], p1[4];
        #pragma unroll
        for (int c = 0; c < 4; c++){
            p0[c] = make_float2(m[c].x + m[4+c].x + m[8+c].x,
                                m[c].y + m[4+c].y + m[8+c].y);
            p1[c] = make_float2(m[4+c].x - m[8+c].x - m[12+c].x,
                                m[4+c].y - m[8+c].y - m[12+c].y);
        }
        float4 r0 = make_float4((p0[0].x+p0[1].x+p0[2].x)*ds, (p0[1].x-p0[2].x-p0[3].x)*ds,
                                (p0[0].y+p0[1].y+p0[2].y)*ds, (p0[1].y-p0[2].y-p0[3].y)*ds);
        float4 r1 = make_float4((p1[0].x+p1[1].x+p1[2].x)*ds, (p1[1].x-p1[2].x-p1[3].x)*ds,
                                (p1[0].y+p1[1].y+p1[2].y)*ds, (p1[1].y-p1[2].y-p1[3].y)*ds);
        *(float4*)(op + (2*i)*64   + jb + 4*sl) = r0;
        *(float4*)(op + (2*i+1)*64 + jb + 4*sl) = r1;
    }
}

// ---------------- launcher ----------------
extern "C" void kernel_launch(void* const* d_in, const int* in_sizes, int n_in,
                              void* d_out, int out_size){
    const float* input      = (const float*)d_in[0];
    const float* style      = (const float*)d_in[1];
    const float* weight     = (const float*)d_in[2];
    const float* mod_weight = (const float*)d_in[3];
    const float* mod_bias   = (const float*)d_in[4];
    float* out = (float*)d_out;

    cudaFuncSetAttribute(gemm_kernel, cudaFuncAttributeMaxDynamicSharedMemorySize, GEMM_SMEM);

    mod_kernel    <<<16, 512>>>(style, mod_weight, mod_bias);
    dtrans_kernel <<<dim3(256,20), 256>>>(input, weight);   // y<16: dtrans, y>=16: fused wtrans
    gemm_kernel   <<<GEMM_GRID, 128, GEMM_SMEM>>>();
    inv_kernel    <<<dim3(256,16), 256>>>(out);
}